// round 4
// baseline (speedup 1.0000x reference)
#include <cuda_runtime.h>
#include <math.h>
#include <stdint.h>

#define BB 16
#define CC 3
#define TT 32
#define HH 224
#define WW 224
#define GS 32
#define GH 7
#define GW 7
#define NPF 49
#define NODES 1568
#define NPATCH 25088
#define NPP 3072
#define NEDGE 15962
#define XFLOATS 250880

__device__ __forceinline__ uint32_t xform(float f) {
    uint32_t u = __float_as_uint(f);
    return (u & 0x80000000u) ? ~u : (u | 0x80000000u);
}
__device__ __forceinline__ float unxform(uint32_t u) {
    u = (u & 0x80000000u) ? (u ^ 0x80000000u) : ~u;
    return __uint_as_float(u);
}

__global__ void __launch_bounds__(256)
feat_kernel(const float* __restrict__ v, float* __restrict__ out)
{
    __shared__ int   hist[2048];          // L1 hist -> cumulative; then 5x128 sections
    __shared__ float rf[48];              // 8 warps x 6 partials
    __shared__ float bc[8];               // S1,S2,S3,S4,mn,mx
    __shared__ int   wsum[8];
    __shared__ int   pfx_s[5], rin_s[5], grp_s[5], uq_s[5];
    __shared__ int   nb_s;

    const int p = blockIdx.x;             // ((b*TT+t)*GH+i)*GW+j
    const int j = p % GW;
    int tmp = p / GW;
    const int i = tmp % GH;
    tmp /= GH;
    const int t = tmp % TT;
    const int b = tmp / TT;

    const int tid  = threadIdx.x;
    const int lane = tid & 31;
    const int warp = tid >> 5;

    #pragma unroll
    for (int z = tid; z < 2048; z += 256) hist[z] = 0;
    __syncthreads();

    // ---- single fused pass: load 12 elems/thread (96 aligned 128B rows),
    //      raw power sums + min/max + xform (kept in registers) + 11-bit hist ----
    uint32_t uu[12];
    float S1 = 0.f, S2 = 0.f, S3 = 0.f, S4 = 0.f;
    float mn = INFINITY, mx = -INFINITY;
    #pragma unroll
    for (int k = 0; k < 12; k++) {
        int r = warp + k * 8;              // 0..95
        int c = r >> 5, y = r & 31;
        size_t base = ((((size_t)b * CC + c) * TT + t) * HH + (size_t)(i * GS + y)) * WW
                      + (size_t)(j * GS);
        float x = v[base + lane];
        float x2 = x * x;
        S1 += x; S2 += x2; S3 += x2 * x; S4 += x2 * x2;
        mn = fminf(mn, x);
        mx = fmaxf(mx, x);
        uint32_t u = xform(x);
        uu[k] = u;
        int bin = (int)(u >> 21);
        unsigned mk = __match_any_sync(0xffffffffu, bin);
        if (lane == (__ffs(mk) - 1)) atomicAdd(&hist[bin], __popc(mk));
    }
    #pragma unroll
    for (int off = 16; off > 0; off >>= 1) {
        S1 += __shfl_down_sync(0xffffffffu, S1, off);
        S2 += __shfl_down_sync(0xffffffffu, S2, off);
        S3 += __shfl_down_sync(0xffffffffu, S3, off);
        S4 += __shfl_down_sync(0xffffffffu, S4, off);
        mn = fminf(mn, __shfl_down_sync(0xffffffffu, mn, off));
        mx = fmaxf(mx, __shfl_down_sync(0xffffffffu, mx, off));
    }
    if (lane == 0) {
        rf[warp] = S1; rf[8 + warp] = S2; rf[16 + warp] = S3;
        rf[24 + warp] = S4; rf[32 + warp] = mn; rf[40 + warp] = mx;
    }
    __syncthreads();
    if (tid == 0) {
        float a = 0.f, b2 = 0.f, c2 = 0.f, d2 = 0.f, MN = INFINITY, MX = -INFINITY;
        #pragma unroll
        for (int w = 0; w < 8; w++) {
            a += rf[w]; b2 += rf[8+w]; c2 += rf[16+w]; d2 += rf[24+w];
            MN = fminf(MN, rf[32+w]); MX = fmaxf(MX, rf[40+w]);
        }
        bc[0] = a; bc[1] = b2; bc[2] = c2; bc[3] = d2; bc[4] = MN; bc[5] = MX;
    }

    // ---- exclusive prefix scan of hist[2048] in place ----
    {
        int base = tid * 8;
        int vals[8];
        int lsum = 0;
        #pragma unroll
        for (int k = 0; k < 8; k++) {
            vals[k] = hist[base + k];
            int tpv = lsum; lsum += vals[k]; vals[k] = tpv;
        }
        int vinc = lsum;
        #pragma unroll
        for (int off = 1; off < 32; off <<= 1) {
            int n = __shfl_up_sync(0xffffffffu, vinc, off);
            if (lane >= off) vinc += n;
        }
        if (lane == 31) wsum[warp] = vinc;
        __syncthreads();
        if (tid == 0) {
            int acc = 0;
            #pragma unroll
            for (int k = 0; k < 8; k++) { int tv = wsum[k]; wsum[k] = acc; acc += tv; }
        }
        __syncthreads();
        int thr_excl = wsum[warp] + (vinc - lsum);
        #pragma unroll
        for (int k = 0; k < 8; k++) hist[base + k] = thr_excl + vals[k];
    }
    __syncthreads();

    // ---- L1 select: 5 parallel binary searches over cumulative hist ----
    if (tid < 5) {
        const int ranks5[5] = {767, 768, 1535, 2303, 2304};
        int r = ranks5[tid];
        int lo = 0, hi = 2047;
        while (lo < hi) {                   // largest bin with cum <= r
            int mid = (lo + hi + 1) >> 1;
            if (hist[mid] <= r) lo = mid; else hi = mid - 1;
        }
        pfx_s[tid] = lo;
        rin_s[tid] = r - hist[lo];
    }
    __syncthreads();

    // ---- 3 refinement rounds of 7 bits each (11+7+7+7 = 32) ----
    #pragma unroll
    for (int round = 0; round < 3; round++) {
        const int sh = 14 - 7 * round;      // low-bit position of this round's 7 bits
        if (tid == 0) {
            int n = 0;
            #pragma unroll
            for (int k = 0; k < 5; k++) {
                if (k == 0 || pfx_s[k] != pfx_s[k - 1]) { uq_s[n] = pfx_s[k]; n++; }
                grp_s[k] = n - 1;
            }
            nb_s = n;
        }
        #pragma unroll
        for (int z = tid; z < 640; z += 256) hist[z] = 0;
        __syncthreads();
        const int nb = nb_s;

        #pragma unroll
        for (int k = 0; k < 12; k++) {
            uint32_t pf = uu[k] >> (sh + 7);
            int bin = (int)((uu[k] >> sh) & 127u);
            for (int q = 0; q < nb; q++) {
                if (pf == (uint32_t)uq_s[q]) { atomicAdd(&hist[q * 128 + bin], 1); break; }
            }
        }
        __syncthreads();

        if (warp < 5) {
            int g = grp_s[warp], r = rin_s[warp];
            int base = g * 128 + lane * 4;
            int c0 = hist[base], c1 = hist[base + 1], c2 = hist[base + 2], c3 = hist[base + 3];
            int ls = c0 + c1 + c2 + c3;
            int inc = ls;
            #pragma unroll
            for (int off = 1; off < 32; off <<= 1) {
                int n = __shfl_up_sync(0xffffffffu, inc, off);
                if (lane >= off) inc += n;
            }
            int excl = inc - ls;
            if (r >= excl && r < excl + ls) {
                int rr = r - excl;
                int bin;
                if (rr < c0)              { bin = 0; }
                else if (rr < c0+c1)      { bin = 1; rr -= c0; }
                else if (rr < c0+c1+c2)   { bin = 2; rr -= c0 + c1; }
                else                      { bin = 3; rr -= c0 + c1 + c2; }
                bin += lane * 4;
                pfx_s[warp] = (pfx_s[warp] << 7) | bin;
                rin_s[warp] = rr;
            }
        }
        __syncthreads();
    }

    if (tid == 0) {
        const double n = (double)NPP;
        double s1 = bc[0], s2 = bc[1], s3 = bc[2], s4 = bc[3];
        double mean = s1 / n;
        double c2 = s2 - n * mean * mean;
        double c3 = s3 - 3.0 * mean * s2 + 2.0 * n * mean * mean * mean;
        double m2s = mean * mean;
        double c4 = s4 - 4.0 * mean * s3 + 6.0 * m2s * s2 - 3.0 * n * m2s * m2s;
        double sd = sqrt(c2 / (n - 1.0));
        double sde = sd + 1e-8;
        double energy = s2 / n;
        double rms = sqrt(energy + 1e-8);
        double i3 = 1.0 / (sde * sde * sde);
        double skew = (c3 / n) * i3;
        double kurt = (c4 / n) * i3 / sde - 3.0;

        float v767 = unxform((uint32_t)pfx_s[0]);
        float v768 = unxform((uint32_t)pfx_s[1]);
        float med  = unxform((uint32_t)pfx_s[2]);
        float v2303 = unxform((uint32_t)pfx_s[3]);
        float v2304 = unxform((uint32_t)pfx_s[4]);
        float q25 = v767 * 0.25f + v768 * 0.75f;
        float q75 = v2303 * 0.75f + v2304 * 0.25f;

        float* o = out + (size_t)p * 10;
        o[0] = (float)mean; o[1] = (float)sd; o[2] = bc[4]; o[3] = bc[5];
        o[4] = (float)energy; o[5] = (float)rms; o[6] = (float)skew;
        o[7] = (float)kurt; o[8] = med; o[9] = q75 - q25;
    }
}

__device__ __forceinline__ int tau_t(int t) {
    int c = 0;
    if (t + 1 < TT) c++;
    if (t - 1 >= 0) c++;
    if (t + 2 < TT) c++;
    if (t - 2 >= 0) c++;
    return c;
}

__global__ void edge_kernel(float* __restrict__ out)
{
    int node = blockIdx.x * blockDim.x + threadIdx.x;
    if (node >= NODES) return;
    int t = node / NPF;
    int rem = node % NPF;
    int i = rem / GW;
    int j = rem % GW;

    int mt = t < 30 ? t : 30;
    int cum_tau = (t > 0 ? 2 : 0) + (t > 1 ? 3 : 0)
                + 4 * (mt > 2 ? (mt - 2) : 0) + (t > 30 ? 3 : 0);
    int taut = tau_t(t);
    int rowpref = (i == 0) ? 0 : (31 + 50 * (i - 1));
    int ci = (i == 0 || i == GH - 1) ? 2 : 3;
    int cumcj = (j > 0 ? 2 : 0) + 3 * (j > 1 ? (j - 1) : 0);
    int sp = rowpref + ci * cumcj - j;
    int off = 312 * t + 49 * cum_tau + sp + rem * taut;

    const int di[8] = {-1,-1,-1, 0, 0, 1, 1, 1};
    const int dj[8] = {-1, 0, 1,-1, 1,-1, 0, 1};
    int e = off;
    float fnode = (float)node;
    #pragma unroll
    for (int q = 0; q < 8; q++) {
        int ni = i + di[q], nj = j + dj[q];
        if (ni >= 0 && ni < GH && nj >= 0 && nj < GW) {
            out[e]         = fnode;
            out[NEDGE + e] = (float)(t * NPF + ni * GW + nj);
            e++;
        }
    }
    const int dts[4] = {1, -1, 2, -2};
    #pragma unroll
    for (int q = 0; q < 4; q++) {
        int tt2 = t + dts[q];
        if (tt2 >= 0 && tt2 < TT) {
            out[e]         = fnode;
            out[NEDGE + e] = (float)(tt2 * NPF + i * GW + j);
            e++;
        }
    }
}

extern "C" void kernel_launch(void* const* d_in, const int* in_sizes, int n_in,
                              void* d_out, int out_size)
{
    const float* video = (const float*)d_in[0];
    float* out = (float*)d_out;

    feat_kernel<<<NPATCH, 256>>>(video, out);

    if (out_size >= XFLOATS + 2 * NEDGE) {
        edge_kernel<<<(NODES + 255) / 256, 256>>>(out + XFLOATS);
    }
}

// round 5
// speedup vs baseline: 1.7368x; 1.7368x over previous
#include <cuda_runtime.h>
#include <math.h>
#include <stdint.h>

#define BB 16
#define CC 3
#define TT 32
#define HH 224
#define WW 224
#define GS 32
#define GH 7
#define GW 7
#define NPF 49
#define NODES 1568
#define NPATCH 25088
#define NPP 3072
#define NEDGE 15962
#define XFLOATS 250880
#define NBIN 2048

__global__ void __launch_bounds__(256)
feat_kernel(const float* __restrict__ v, float* __restrict__ out)
{
    __shared__ int   hist[NBIN];          // counts -> exclusive cumulative in place
    __shared__ float cand[NPP];           // candidate values (worst-case capacity)
    __shared__ float rf[48];
    __shared__ float bc[8];               // S1,S2,S3,S4,mn,mx
    __shared__ int   wsum[8];
    __shared__ int   bin_s[5], rin_s[5], cnt_s[5], grp_s[5];
    __shared__ int   uq_s[5], seg_off[5], dcur[5];
    __shared__ int   nb_s;
    __shared__ float resv[5];

    const int p = blockIdx.x;             // ((b*TT+t)*GH+i)*GW+j
    const int j = p % GW;
    int tmp = p / GW;
    const int i = tmp % GH;
    tmp /= GH;
    const int t = tmp % TT;
    const int b = tmp / TT;

    const int tid  = threadIdx.x;
    const int lane = tid & 31;
    const int warp = tid >> 5;

    #pragma unroll
    for (int z = tid; z < NBIN; z += 256) hist[z] = 0;

    // ---- load 12 floats/thread as 3 x float4 (coalesced 128B rows) ----
    // warp w covers patch-rows [w*12, w*12+12); per load: 4 rows (8 lanes x float4 each)
    float uu[12];
    float S1 = 0.f, S2 = 0.f, S3 = 0.f, S4 = 0.f;
    float mn = INFINITY, mx = -INFINITY;
    const int sub = lane & 7;             // float4 slot within row
    const int rgrp = lane >> 3;           // row within 4-row group
    #pragma unroll
    for (int k = 0; k < 3; k++) {
        int r = warp * 12 + k * 4 + rgrp; // 0..95
        int c = r >> 5, y = r & 31;
        size_t base = ((((size_t)b * CC + c) * TT + t) * HH + (size_t)(i * GS + y)) * WW
                      + (size_t)(j * GS) + (size_t)(sub * 4);
        float4 x4 = *reinterpret_cast<const float4*>(v + base);
        float xs[4] = {x4.x, x4.y, x4.z, x4.w};
        #pragma unroll
        for (int e = 0; e < 4; e++) {
            float x = xs[e];
            float x2 = x * x;
            S1 += x; S2 += x2; S3 += x2 * x; S4 += x2 * x2;
            mn = fminf(mn, x);
            mx = fmaxf(mx, x);
            uu[k * 4 + e] = x;
        }
    }
    #pragma unroll
    for (int off = 16; off > 0; off >>= 1) {
        S1 += __shfl_down_sync(0xffffffffu, S1, off);
        S2 += __shfl_down_sync(0xffffffffu, S2, off);
        S3 += __shfl_down_sync(0xffffffffu, S3, off);
        S4 += __shfl_down_sync(0xffffffffu, S4, off);
        mn = fminf(mn, __shfl_down_sync(0xffffffffu, mn, off));
        mx = fmaxf(mx, __shfl_down_sync(0xffffffffu, mx, off));
    }
    if (lane == 0) {
        rf[warp] = S1; rf[8 + warp] = S2; rf[16 + warp] = S3;
        rf[24 + warp] = S4; rf[32 + warp] = mn; rf[40 + warp] = mx;
    }
    __syncthreads();
    if (tid == 0) {
        float a = 0.f, b2 = 0.f, c2 = 0.f, d2 = 0.f, MN = INFINITY, MX = -INFINITY;
        #pragma unroll
        for (int w = 0; w < 8; w++) {
            a += rf[w]; b2 += rf[8+w]; c2 += rf[16+w]; d2 += rf[24+w];
            MN = fminf(MN, rf[32+w]); MX = fmaxf(MX, rf[40+w]);
        }
        bc[0] = a; bc[1] = b2; bc[2] = c2; bc[3] = d2; bc[4] = MN; bc[5] = MX;
    }
    __syncthreads();
    const float MN = bc[4];
    const float MX = bc[5];
    const float scale = (MX > MN) ? ((float)NBIN - 0.01f) / (MX - MN) : 0.0f;

    // ---- linear-bin histogram (bins spread across smem -> raw atomics) ----
    int ub[12];
    #pragma unroll
    for (int k = 0; k < 12; k++) {
        int bin = (int)((uu[k] - MN) * scale);
        bin = min(max(bin, 0), NBIN - 1);
        ub[k] = bin;
        atomicAdd(&hist[bin], 1);
    }
    __syncthreads();

    // ---- exclusive prefix scan of hist[2048] in place ----
    {
        int base = tid * 8;
        int vals[8];
        int lsum = 0;
        #pragma unroll
        for (int k = 0; k < 8; k++) {
            vals[k] = hist[base + k];
            int tpv = lsum; lsum += vals[k]; vals[k] = tpv;
        }
        int vinc = lsum;
        #pragma unroll
        for (int off = 1; off < 32; off <<= 1) {
            int n = __shfl_up_sync(0xffffffffu, vinc, off);
            if (lane >= off) vinc += n;
        }
        if (lane == 31) wsum[warp] = vinc;
        __syncthreads();
        if (tid == 0) {
            int acc = 0;
            #pragma unroll
            for (int k = 0; k < 8; k++) { int tv = wsum[k]; wsum[k] = acc; acc += tv; }
        }
        __syncthreads();
        int thr_excl = wsum[warp] + (vinc - lsum);
        #pragma unroll
        for (int k = 0; k < 8; k++) hist[base + k] = thr_excl + vals[k];
    }
    __syncthreads();

    // ---- 5 parallel binary searches over cumulative hist ----
    if (tid < 5) {
        const int ranks5[5] = {767, 768, 1535, 2303, 2304};
        int r = ranks5[tid];
        int lo = 0, hi = NBIN - 1;
        while (lo < hi) {                  // largest bin with cum <= r
            int mid = (lo + hi + 1) >> 1;
            if (hist[mid] <= r) lo = mid; else hi = mid - 1;
        }
        bin_s[tid] = lo;
        rin_s[tid] = r - hist[lo];
        cnt_s[tid] = ((lo == NBIN - 1) ? NPP : hist[lo + 1]) - hist[lo];
    }
    __syncthreads();

    // ---- segment setup (dedup target bins) ----
    if (tid == 0) {
        int nbv = 0, off = 0;
        #pragma unroll
        for (int k = 0; k < 5; k++) {
            if (k == 0 || bin_s[k] != bin_s[k - 1]) {
                uq_s[nbv] = bin_s[k]; seg_off[nbv] = off; dcur[nbv] = 0;
                off += cnt_s[k]; nbv++;
            }
            grp_s[k] = nbv - 1;
        }
        nb_s = nbv;
    }
    __syncthreads();
    const int nb = nb_s;

    // ---- collect candidate elements of target bins ----
    #pragma unroll
    for (int k = 0; k < 12; k++) {
        int bin = ub[k];
        #pragma unroll 5
        for (int q = 0; q < nb; q++) {
            if (bin == uq_s[q]) {
                int pos = atomicAdd(&dcur[q], 1);
                cand[seg_off[q] + pos] = uu[k];
                break;
            }
        }
    }
    __syncthreads();

    // ---- exact rank within candidate segment (warp k handles rank k) ----
    if (warp < 5) {
        int g = grp_s[warp];
        int r = rin_s[warp];
        int off = seg_off[g];
        int cnt = dcur[g];
        for (int idx = lane; idx < cnt; idx += 32) {
            float key = cand[off + idx];
            int less = 0, eq = 0;
            for (int m = 0; m < cnt; m++) {
                float c = cand[off + m];
                less += (c < key);
                eq   += (c == key);
            }
            if (r >= less && r < less + eq) resv[warp] = key;
        }
    }
    __syncthreads();

    if (tid == 0) {
        const double n = (double)NPP;
        double s1 = bc[0], s2 = bc[1], s3 = bc[2], s4 = bc[3];
        double mean = s1 / n;
        double c2 = s2 - n * mean * mean;
        double c3 = s3 - 3.0 * mean * s2 + 2.0 * n * mean * mean * mean;
        double m2s = mean * mean;
        double c4 = s4 - 4.0 * mean * s3 + 6.0 * m2s * s2 - 3.0 * n * m2s * m2s;
        double sd = sqrt(c2 / (n - 1.0));
        double sde = sd + 1e-8;
        double energy = s2 / n;
        double rms = sqrt(energy + 1e-8);
        double i3 = 1.0 / (sde * sde * sde);
        double skew = (c3 / n) * i3;
        double kurt = (c4 / n) * i3 / sde - 3.0;

        float q25 = resv[0] * 0.25f + resv[1] * 0.75f;
        float q75 = resv[3] * 0.75f + resv[4] * 0.25f;

        float* o = out + (size_t)p * 10;
        o[0] = (float)mean; o[1] = (float)sd; o[2] = MN; o[3] = MX;
        o[4] = (float)energy; o[5] = (float)rms; o[6] = (float)skew;
        o[7] = (float)kurt; o[8] = resv[2]; o[9] = q25 <= q75 ? (q75 - q25) : (q75 - q25);
    }
}

__device__ __forceinline__ int tau_t(int t) {
    int c = 0;
    if (t + 1 < TT) c++;
    if (t - 1 >= 0) c++;
    if (t + 2 < TT) c++;
    if (t - 2 >= 0) c++;
    return c;
}

__global__ void edge_kernel(float* __restrict__ out)
{
    int node = blockIdx.x * blockDim.x + threadIdx.x;
    if (node >= NODES) return;
    int t = node / NPF;
    int rem = node % NPF;
    int i = rem / GW;
    int j = rem % GW;

    int mt = t < 30 ? t : 30;
    int cum_tau = (t > 0 ? 2 : 0) + (t > 1 ? 3 : 0)
                + 4 * (mt > 2 ? (mt - 2) : 0) + (t > 30 ? 3 : 0);
    int taut = tau_t(t);
    int rowpref = (i == 0) ? 0 : (31 + 50 * (i - 1));
    int ci = (i == 0 || i == GH - 1) ? 2 : 3;
    int cumcj = (j > 0 ? 2 : 0) + 3 * (j > 1 ? (j - 1) : 0);
    int sp = rowpref + ci * cumcj - j;
    int off = 312 * t + 49 * cum_tau + sp + rem * taut;

    const int di[8] = {-1,-1,-1, 0, 0, 1, 1, 1};
    const int dj[8] = {-1, 0, 1,-1, 1,-1, 0, 1};
    int e = off;
    float fnode = (float)node;
    #pragma unroll
    for (int q = 0; q < 8; q++) {
        int ni = i + di[q], nj = j + dj[q];
        if (ni >= 0 && ni < GH && nj >= 0 && nj < GW) {
            out[e]         = fnode;
            out[NEDGE + e] = (float)(t * NPF + ni * GW + nj);
            e++;
        }
    }
    const int dts[4] = {1, -1, 2, -2};
    #pragma unroll
    for (int q = 0; q < 4; q++) {
        int tt2 = t + dts[q];
        if (tt2 >= 0 && tt2 < TT) {
            out[e]         = fnode;
            out[NEDGE + e] = (float)(tt2 * NPF + i * GW + j);
            e++;
        }
    }
}

extern "C" void kernel_launch(void* const* d_in, const int* in_sizes, int n_in,
                              void* d_out, int out_size)
{
    const float* video = (const float*)d_in[0];
    float* out = (float*)d_out;

    feat_kernel<<<NPATCH, 256>>>(video, out);

    if (out_size >= XFLOATS + 2 * NEDGE) {
        edge_kernel<<<(NODES + 255) / 256, 256>>>(out + XFLOATS);
    }
}

// round 6
// speedup vs baseline: 1.9961x; 1.1493x over previous
#include <cuda_runtime.h>
#include <math.h>
#include <stdint.h>

#define BB 16
#define CC 3
#define TT 32
#define HH 224
#define WW 224
#define GS 32
#define GH 7
#define GW 7
#define NPF 49
#define NODES 1568
#define NPATCH 25088
#define NPP 3072
#define NEDGE 15962
#define XFLOATS 250880
#define WPB 2
#define CAP 96

__device__ __forceinline__ float wsumf(float x) {
    #pragma unroll
    for (int o = 16; o; o >>= 1) x += __shfl_xor_sync(0xffffffffu, x, o);
    return x;
}
__device__ __forceinline__ int wsumi(int x) {
    #pragma unroll
    for (int o = 16; o; o >>= 1) x += __shfl_xor_sync(0xffffffffu, x, o);
    return x;
}
__device__ __forceinline__ float wminf(float x) {
    #pragma unroll
    for (int o = 16; o; o >>= 1) x = fminf(x, __shfl_xor_sync(0xffffffffu, x, o));
    return x;
}
__device__ __forceinline__ float wmaxf(float x) {
    #pragma unroll
    for (int o = 16; o; o >>= 1) x = fmaxf(x, __shfl_xor_sync(0xffffffffu, x, o));
    return x;
}

// warp-uniform count of elements < piv
__device__ __forceinline__ int count_less(const float* sp, int lane, float piv) {
    int c = 0;
    #pragma unroll 4
    for (int m = 0; m < 24; m++) {
        float4 x4 = *reinterpret_cast<const float4*>(sp + m * 128 + lane * 4);
        c += (x4.x < piv) + (x4.y < piv) + (x4.z < piv) + (x4.w < piv);
    }
    return wsumi(c);
}

// gather elements in [glo, ghi) into buf (clamped at cap); returns true in-range count
__device__ __forceinline__ int gather_range(const float* sp, float* buf, int lane,
                                            float glo, float ghi, int cap) {
    int cnt = 0;
    unsigned lt = (1u << lane) - 1u;
    #pragma unroll 2
    for (int m = 0; m < 24; m++) {
        float4 x4 = *reinterpret_cast<const float4*>(sp + m * 128 + lane * 4);
        float xs[4] = {x4.x, x4.y, x4.z, x4.w};
        #pragma unroll
        for (int e = 0; e < 4; e++) {
            float x = xs[e];
            bool inb = (x >= glo) && (x < ghi);
            unsigned mk = __ballot_sync(0xffffffffu, inb);
            if (inb) {
                int pos = cnt + __popc(mk & lt);
                if (pos < cap) buf[pos] = x;
            }
            cnt += __popc(mk);
        }
    }
    return cnt;
}

// tie-aware exact select of two ranks rr0, rr1 (0-based) within buf[0..cnt)
__device__ __forceinline__ void select2(const float* buf, int cnt, int rr0, int rr1,
                                        int lane, float* o0, float* o1) {
    float a0 = 0.f, a1 = 0.f;
    bool f0 = false, f1 = false;
    for (int idx = lane; idx < cnt; idx += 32) {
        float v = buf[idx];
        int less = 0, eq = 0;
        for (int m = 0; m < cnt; m++) {
            float c = buf[m];
            less += (c < v);
            eq   += (c == v);
        }
        if (rr0 >= less && rr0 < less + eq) { a0 = v; f0 = true; }
        if (rr1 >= less && rr1 < less + eq) { a1 = v; f1 = true; }
    }
    unsigned m0 = __ballot_sync(0xffffffffu, f0);
    unsigned m1 = __ballot_sync(0xffffffffu, f1);
    int s0 = m0 ? (__ffs(m0) - 1) : 0;
    int s1 = m1 ? (__ffs(m1) - 1) : 0;
    *o0 = __shfl_sync(0xffffffffu, a0, s0);
    *o1 = __shfl_sync(0xffffffffu, a1, s1);
}

// guaranteed-exact single-rank selection via value bisection (rare fallback)
__device__ float select_slow(const float* sp, float* buf, int lane, int k,
                             float mn, float mx) {
    float lo = mn, hi = nextafterf(mx, INFINITY);
    int clo = 0;
    for (int it = 0; it < 80; it++) {
        int ch = count_less(sp, lane, hi);
        int cnt = ch - clo;
        if (cnt <= CAP) {
            int g = gather_range(sp, buf, lane, lo, hi, CAP);
            __syncwarp();
            float r0, r1;
            select2(buf, g < CAP ? g : CAP, k - clo, k - clo, lane, &r0, &r1);
            return r0;
        }
        float mid = 0.5f * (lo + hi);
        if (!(mid > lo && mid < hi)) return lo;   // 1-ulp interval: all equal
        int cm = count_less(sp, lane, mid);
        if (k < cm) hi = mid; else { lo = mid; clo = cm; }
    }
    return lo;
}

__global__ void __launch_bounds__(64)
feat_kernel(const float* __restrict__ v, float* __restrict__ out)
{
    __shared__ __align__(16) float patch[WPB][NPP];
    __shared__ float cbuf[WPB][3][CAP];

    const int lane = threadIdx.x & 31;
    const int warp = threadIdx.x >> 5;
    const int p = blockIdx.x * WPB + warp;   // ((b*TT+t)*GH+i)*GW+j
    const int j = p % GW;
    int tmp = p / GW;
    const int i = tmp % GH;
    tmp /= GH;
    const int t = tmp % TT;
    const int b = tmp / TT;

    float* sp = patch[warp];
    const int sub = lane & 7, rg = lane >> 3;

    // ---- load 96 rows x 32 floats (24 x LDG.128/lane): moments + min/max + smem ----
    float S1 = 0.f, S2 = 0.f, S3 = 0.f, S4 = 0.f;
    float mn = INFINITY, mx = -INFINITY;
    #pragma unroll 6
    for (int k = 0; k < 24; k++) {
        int r = k * 4 + rg;                   // 0..95
        int c = r >> 5, y = r & 31;
        size_t base = ((((size_t)b * CC + c) * TT + t) * HH + (size_t)(i * GS + y)) * WW
                      + (size_t)(j * GS) + (size_t)(sub * 4);
        float4 x4 = *reinterpret_cast<const float4*>(v + base);
        float xs[4] = {x4.x, x4.y, x4.z, x4.w};
        #pragma unroll
        for (int e = 0; e < 4; e++) {
            float x = xs[e];
            float x2 = x * x;
            S1 += x; S2 += x2; S3 += x2 * x; S4 += x2 * x2;
            mn = fminf(mn, x);
            mx = fmaxf(mx, x);
        }
        *reinterpret_cast<float4*>(sp + r * 32 + sub * 4) = x4;
    }
    S1 = wsumf(S1); S2 = wsumf(S2); S3 = wsumf(S3); S4 = wsumf(S4);
    mn = wminf(mn); mx = wmaxf(mx);
    __syncwarp();

    const float meanf = S1 * (1.0f / (float)NPP);
    const float sdf = sqrtf(fmaxf((S2 - (float)NPP * meanf * meanf) / ((float)NPP - 1.f), 0.f));

    float q0, q1, q2, q3, q4;                 // v767, v768, med, v2303, v2304
    if (mx == mn) {
        q0 = q1 = q2 = q3 = q4 = mn;
    } else {
        const float Z0 = -0.67448975f, Z2 = 0.67448975f;
        const int RA0 = 767, RB0 = 768, RA1 = 1535, RA2 = 2303, RB2 = 2304;

        // ---- pass 1: count below 6 pivots, widen until all ranks bracketed ----
        float plo0, phi0, plo1, phi1, plo2, phi2;
        int cl0, ch0, cl1, ch1, cl2, ch2;
        float D = 0.12f;
        bool ok = false;
        for (int att = 0; att < 24 && !ok; att++) {
            if (att < 4) {
                plo0 = meanf + (Z0 - D) * sdf; phi0 = meanf + (Z0 + D) * sdf;
                plo1 = meanf + (-D) * sdf;     phi1 = meanf + (D) * sdf;
                plo2 = meanf + (Z2 - D) * sdf; phi2 = meanf + (Z2 + D) * sdf;
            } else {
                float hiall = nextafterf(mx, INFINITY);
                plo0 = plo1 = plo2 = mn;
                phi0 = phi1 = phi2 = hiall;
            }
            int a0 = 0, b0 = 0, a1 = 0, b1 = 0, a2 = 0, b2 = 0;
            #pragma unroll 2
            for (int m = 0; m < 24; m++) {
                float4 x4 = *reinterpret_cast<const float4*>(sp + m * 128 + lane * 4);
                float xs[4] = {x4.x, x4.y, x4.z, x4.w};
                #pragma unroll
                for (int e = 0; e < 4; e++) {
                    float x = xs[e];
                    a0 += (x < plo0); b0 += (x < phi0);
                    a1 += (x < plo1); b1 += (x < phi1);
                    a2 += (x < plo2); b2 += (x < phi2);
                }
            }
            cl0 = wsumi(a0); ch0 = wsumi(b0);
            cl1 = wsumi(a1); ch1 = wsumi(b1);
            cl2 = wsumi(a2); ch2 = wsumi(b2);
            ok = (cl0 <= RA0 && ch0 > RB0) && (cl1 <= RA1 && ch1 > RA1)
              && (cl2 <= RA2 && ch2 > RB2);
            D *= 2.0f;
        }

        // ---- interpolate tight brackets (~±22 ranks) ----
        float glo0, ghi0, glo1, ghi1, glo2, ghi2;
        {
            float w0 = phi0 - plo0, w1 = phi1 - plo1, w2 = phi2 - plo2;
            float ci0 = (float)(ch0 - cl0), ci1 = (float)(ch1 - cl1), ci2 = (float)(ch2 - cl2);
            float v0 = plo0 + ((767.5f + 0.5f) - (float)cl0) / ci0 * w0;
            float v1 = plo1 + ((1535.0f + 0.5f) - (float)cl1) / ci1 * w1;
            float v2 = plo2 + ((2303.5f + 0.5f) - (float)cl2) / ci2 * w2;
            float d0 = 22.f * w0 / ci0, d1 = 22.f * w1 / ci1, d2 = 22.f * w2 / ci2;
            glo0 = v0 - d0; ghi0 = v0 + d0;
            glo1 = v1 - d1; ghi1 = v1 + d1;
            glo2 = v2 - d2; ghi2 = v2 + d2;
        }

        // ---- pass 2: fused count(<glo) + gather into per-region buffers ----
        int c2l0 = 0, c2l1 = 0, c2l2 = 0;
        int g0 = 0, g1 = 0, g2 = 0;
        unsigned lt = (1u << lane) - 1u;
        #pragma unroll 2
        for (int m = 0; m < 24; m++) {
            float4 x4 = *reinterpret_cast<const float4*>(sp + m * 128 + lane * 4);
            float xs[4] = {x4.x, x4.y, x4.z, x4.w};
            #pragma unroll
            for (int e = 0; e < 4; e++) {
                float x = xs[e];
                bool lo_a = x < glo0;
                bool in0 = !lo_a && (x < ghi0);
                c2l0 += lo_a;
                unsigned mk0 = __ballot_sync(0xffffffffu, in0);
                if (in0) { int pos = g0 + __popc(mk0 & lt); if (pos < CAP) cbuf[warp][0][pos] = x; }
                g0 += __popc(mk0);

                bool lo_b = x < glo1;
                bool in1 = !lo_b && (x < ghi1);
                c2l1 += lo_b;
                unsigned mk1 = __ballot_sync(0xffffffffu, in1);
                if (in1) { int pos = g1 + __popc(mk1 & lt); if (pos < CAP) cbuf[warp][1][pos] = x; }
                g1 += __popc(mk1);

                bool lo_c = x < glo2;
                bool in2 = !lo_c && (x < ghi2);
                c2l2 += lo_c;
                unsigned mk2 = __ballot_sync(0xffffffffu, in2);
                if (in2) { int pos = g2 + __popc(mk2 & lt); if (pos < CAP) cbuf[warp][2][pos] = x; }
                g2 += __popc(mk2);
            }
        }
        c2l0 = wsumi(c2l0); c2l1 = wsumi(c2l1); c2l2 = wsumi(c2l2);
        __syncwarp();

        // ---- exact selects (fast path) / bisection fallback ----
        if (g0 <= CAP && RA0 >= c2l0 && RB0 < c2l0 + g0) {
            select2(cbuf[warp][0], g0, RA0 - c2l0, RB0 - c2l0, lane, &q0, &q1);
        } else {
            q0 = select_slow(sp, cbuf[warp][0], lane, RA0, mn, mx);
            q1 = select_slow(sp, cbuf[warp][0], lane, RB0, mn, mx);
        }
        if (g1 <= CAP && RA1 >= c2l1 && RA1 < c2l1 + g1) {
            float d0;
            select2(cbuf[warp][1], g1, RA1 - c2l1, RA1 - c2l1, lane, &q2, &d0);
        } else {
            q2 = select_slow(sp, cbuf[warp][1], lane, RA1, mn, mx);
        }
        if (g2 <= CAP && RA2 >= c2l2 && RB2 < c2l2 + g2) {
            select2(cbuf[warp][2], g2, RA2 - c2l2, RB2 - c2l2, lane, &q3, &q4);
        } else {
            q3 = select_slow(sp, cbuf[warp][2], lane, RA2, mn, mx);
            q4 = select_slow(sp, cbuf[warp][2], lane, RB2, mn, mx);
        }
    }

    if (lane == 0) {
        const double n = (double)NPP;
        double s1 = S1, s2 = S2, s3 = S3, s4 = S4;
        double mean = s1 / n;
        double c2 = s2 - n * mean * mean;
        double c3 = s3 - 3.0 * mean * s2 + 2.0 * n * mean * mean * mean;
        double m2s = mean * mean;
        double c4 = s4 - 4.0 * mean * s3 + 6.0 * m2s * s2 - 3.0 * n * m2s * m2s;
        double sd = sqrt(c2 / (n - 1.0));
        double sde = sd + 1e-8;
        double energy = s2 / n;
        double rms = sqrt(energy + 1e-8);
        double i3 = 1.0 / (sde * sde * sde);
        double skew = (c3 / n) * i3;
        double kurt = (c4 / n) * i3 / sde - 3.0;
        float q25 = q0 * 0.25f + q1 * 0.75f;
        float q75 = q3 * 0.75f + q4 * 0.25f;

        float* o = out + (size_t)p * 10;
        o[0] = (float)mean; o[1] = (float)sd; o[2] = mn; o[3] = mx;
        o[4] = (float)energy; o[5] = (float)rms; o[6] = (float)skew;
        o[7] = (float)kurt; o[8] = q2; o[9] = q75 - q25;
    }
}

__device__ __forceinline__ int tau_t(int t) {
    int c = 0;
    if (t + 1 < TT) c++;
    if (t - 1 >= 0) c++;
    if (t + 2 < TT) c++;
    if (t - 2 >= 0) c++;
    return c;
}

__global__ void edge_kernel(float* __restrict__ out)
{
    int node = blockIdx.x * blockDim.x + threadIdx.x;
    if (node >= NODES) return;
    int t = node / NPF;
    int rem = node % NPF;
    int i = rem / GW;
    int j = rem % GW;

    int mt = t < 30 ? t : 30;
    int cum_tau = (t > 0 ? 2 : 0) + (t > 1 ? 3 : 0)
                + 4 * (mt > 2 ? (mt - 2) : 0) + (t > 30 ? 3 : 0);
    int taut = tau_t(t);
    int rowpref = (i == 0) ? 0 : (31 + 50 * (i - 1));
    int ci = (i == 0 || i == GH - 1) ? 2 : 3;
    int cumcj = (j > 0 ? 2 : 0) + 3 * (j > 1 ? (j - 1) : 0);
    int sp = rowpref + ci * cumcj - j;
    int off = 312 * t + 49 * cum_tau + sp + rem * taut;

    const int di[8] = {-1,-1,-1, 0, 0, 1, 1, 1};
    const int dj[8] = {-1, 0, 1,-1, 1,-1, 0, 1};
    int e = off;
    float fnode = (float)node;
    #pragma unroll
    for (int q = 0; q < 8; q++) {
        int ni = i + di[q], nj = j + dj[q];
        if (ni >= 0 && ni < GH && nj >= 0 && nj < GW) {
            out[e]         = fnode;
            out[NEDGE + e] = (float)(t * NPF + ni * GW + nj);
            e++;
        }
    }
    const int dts[4] = {1, -1, 2, -2};
    #pragma unroll
    for (int q = 0; q < 4; q++) {
        int tt2 = t + dts[q];
        if (tt2 >= 0 && tt2 < TT) {
            out[e]         = fnode;
            out[NEDGE + e] = (float)(tt2 * NPF + i * GW + j);
            e++;
        }
    }
}

extern "C" void kernel_launch(void* const* d_in, const int* in_sizes, int n_in,
                              void* d_out, int out_size)
{
    const float* video = (const float*)d_in[0];
    float* out = (float*)d_out;

    // edge first: makes ncu's "-s 5 -c 1" land on feat_kernel next profile
    if (out_size >= XFLOATS + 2 * NEDGE) {
        edge_kernel<<<(NODES + 255) / 256, 256>>>(out + XFLOATS);
    }
    feat_kernel<<<NPATCH / WPB, 64>>>(video, out);
}